// round 13
// baseline (speedup 1.0000x reference)
#include <cuda_runtime.h>
#include <cstdint>

// out[tok, :] = sum_{l=0..7} weight[l, x[tok, l], :]
//   x:      16384 tokens x 8 int32 indices
//   weight: (8, 1024, 1024) f32, 32 MB (L2-resident)
//   out:    16384 x 1024 f32
//
// R6 shape (1 CTA/token, 256 thr, 8 CTAs/SM, 8-deep batched LDG.128,
// .cs streaming store) but weight loads use L1::no_allocate: per-SM L1
// reuse of weight rows is ~nil (row reuse is scattered across SMs by CTA
// placement), so skipping L1 allocation removes the fill-write half of
// the L1 data-array traffic — the binding pipe at ~72%.

static constexpr int NTOK = 8 * 2048;   // 16384
static constexpr int K    = 1024;
static constexpr int D4   = 1024 / 4;   // 256 float4 per row

__device__ __forceinline__ float4 ldg_stream(const float4* p)
{
    float4 v;
    asm volatile("ld.global.nc.L1::no_allocate.v4.f32 {%0, %1, %2, %3}, [%4];"
                 : "=f"(v.x), "=f"(v.y), "=f"(v.z), "=f"(v.w)
                 : "l"(p));
    return v;
}

__global__ __launch_bounds__(256, 8)
void multi_embed_kernel(const int4* __restrict__ x4,
                        const float4* __restrict__ w,
                        float4* __restrict__ out)
{
    const int tok = blockIdx.x;
    const int tid = threadIdx.x;

    // All 8 indices via two uniform 16B loads (warp-broadcast).
    const int4 iA = __ldg(x4 + tok * 2);       // l = 0..3
    const int4 iB = __ldg(x4 + tok * 2 + 1);   // l = 4..7

    const float4* wt = w + tid;

    // 8 independent LDG.128 front-batched (MLP=8), no L1 allocation.
    float4 a0 = ldg_stream(wt + (size_t)(0 * K + iA.x) * D4);
    float4 a1 = ldg_stream(wt + (size_t)(1 * K + iA.y) * D4);
    float4 a2 = ldg_stream(wt + (size_t)(2 * K + iA.z) * D4);
    float4 a3 = ldg_stream(wt + (size_t)(3 * K + iA.w) * D4);
    float4 b0 = ldg_stream(wt + (size_t)(4 * K + iB.x) * D4);
    float4 b1 = ldg_stream(wt + (size_t)(5 * K + iB.y) * D4);
    float4 b2 = ldg_stream(wt + (size_t)(6 * K + iB.z) * D4);
    float4 b3 = ldg_stream(wt + (size_t)(7 * K + iB.w) * D4);

    float4 acc;
    acc.x = (a0.x + a1.x) + (a2.x + a3.x);
    acc.y = (a0.y + a1.y) + (a2.y + a3.y);
    acc.z = (a0.z + a1.z) + (a2.z + a3.z);
    acc.w = (a0.w + a1.w) + (a2.w + a3.w);

    acc.x += (b0.x + b1.x) + (b2.x + b3.x);
    acc.y += (b0.y + b1.y) + (b2.y + b3.y);
    acc.z += (b0.z + b1.z) + (b2.z + b3.z);
    acc.w += (b0.w + b1.w) + (b2.w + b3.w);

    // Streaming store: evict-first, don't displace weight lines in L2.
    float4* dst = out + (size_t)tok * D4 + tid;
    asm volatile("st.global.cs.v4.f32 [%0], {%1, %2, %3, %4};"
                 :: "l"(dst), "f"(acc.x), "f"(acc.y), "f"(acc.z), "f"(acc.w)
                 : "memory");
}

extern "C" void kernel_launch(void* const* d_in, const int* in_sizes, int n_in,
                              void* d_out, int out_size)
{
    const int4*   x = (const int4*)d_in[0];
    const float4* w = (const float4*)d_in[1];
    float4*       o = (float4*)d_out;

    multi_embed_kernel<<<NTOK, 256>>>(x, w, o);
}